// round 2
// baseline (speedup 1.0000x reference)
#include <cuda_runtime.h>
#include <math_constants.h>

// Problem constants
#define NROWS 8192
#define NCOLS 4096
#define EPSF 1e-12f

// ---------------------------------------------------------------------------
// Scratch (static device globals; no dynamic allocation allowed)
// ---------------------------------------------------------------------------
__device__ float  g_px[(size_t)NROWS * NCOLS];   // softmax(act_X)
__device__ float  g_py[(size_t)NROWS * NCOLS];   // softmax(act_Y)
__device__ float  g_rowent[NROWS];               // per-row entropy of X
__device__ float  g_margpart[2][32][NCOLS];      // chunked column partial sums
__device__ float  g_lm[2][NCOLS];                // log(marg + eps) for X (0), Y (1)
__device__ double g_mi;                          // MI accumulator

// ---------------------------------------------------------------------------
// Kernel 0: reset accumulators (graph is replayed; globals persist)
// ---------------------------------------------------------------------------
__global__ void init_kernel() {
    g_mi = 0.0;
}

// ---------------------------------------------------------------------------
// Kernel 1: row softmax for X and Y (one block per row), fused entropy for X.
// entropy_row = log(Z) - S/Z  with  Z = sum exp(x-m),  S = sum (x-m)exp(x-m)
// ---------------------------------------------------------------------------
__global__ __launch_bounds__(256) void softmax_kernel(const float* __restrict__ X,
                                                      const float* __restrict__ Y) {
    const int row  = blockIdx.x;              // 0 .. 2*NROWS-1
    const bool isX = row < NROWS;
    const int r    = isX ? row : row - NROWS;
    const float* __restrict__ src = (isX ? X : Y) + (size_t)r * NCOLS;
    float* __restrict__ dst       = (isX ? g_px : g_py) + (size_t)r * NCOLS;

    const int tid = threadIdx.x;              // 256 threads, 16 elems each
    float4 v[4];
#pragma unroll
    for (int i = 0; i < 4; i++)
        v[i] = reinterpret_cast<const float4*>(src)[tid + i * 256];

    // ---- block max ----
    float m = -CUDART_INF_F;
#pragma unroll
    for (int i = 0; i < 4; i++) {
        m = fmaxf(m, fmaxf(fmaxf(v[i].x, v[i].y), fmaxf(v[i].z, v[i].w)));
    }
    __shared__ float sh_max[8];
#pragma unroll
    for (int o = 16; o > 0; o >>= 1) m = fmaxf(m, __shfl_xor_sync(0xffffffffu, m, o));
    if ((tid & 31) == 0) sh_max[tid >> 5] = m;
    __syncthreads();
    m = sh_max[0];
#pragma unroll
    for (int i = 1; i < 8; i++) m = fmaxf(m, sh_max[i]);
    __syncthreads();

    // ---- exp, Z, S ----
    float z = 0.f, s = 0.f;
#pragma unroll
    for (int i = 0; i < 4; i++) {
        float t0 = v[i].x - m, t1 = v[i].y - m, t2 = v[i].z - m, t3 = v[i].w - m;
        float e0 = __expf(t0), e1 = __expf(t1), e2 = __expf(t2), e3 = __expf(t3);
        z += (e0 + e1) + (e2 + e3);
        s += (e0 * t0 + e1 * t1) + (e2 * t2 + e3 * t3);
        v[i].x = e0; v[i].y = e1; v[i].z = e2; v[i].w = e3;
    }
    __shared__ float sh_z[8], sh_s[8];
#pragma unroll
    for (int o = 16; o > 0; o >>= 1) {
        z += __shfl_xor_sync(0xffffffffu, z, o);
        s += __shfl_xor_sync(0xffffffffu, s, o);
    }
    if ((tid & 31) == 0) { sh_z[tid >> 5] = z; sh_s[tid >> 5] = s; }
    __syncthreads();
    z = 0.f; s = 0.f;
#pragma unroll
    for (int i = 0; i < 8; i++) { z += sh_z[i]; s += sh_s[i]; }

    const float invz = 1.0f / z;
#pragma unroll
    for (int i = 0; i < 4; i++) {
        float4 p;
        p.x = v[i].x * invz; p.y = v[i].y * invz;
        p.z = v[i].z * invz; p.w = v[i].w * invz;
        reinterpret_cast<float4*>(dst)[tid + i * 256] = p;
    }

    if (isX && tid == 0)
        g_rowent[r] = logf(z) - s * invz;
}

// ---------------------------------------------------------------------------
// Kernel 2: chunked column sums (deterministic partials, no atomics)
// grid: (NCOLS/256, 32 row-chunks, 2 arrays)
// ---------------------------------------------------------------------------
__global__ __launch_bounds__(256) void marg_kernel() {
    const int col   = blockIdx.x * 256 + threadIdx.x;
    const int chunk = blockIdx.y;   // 32 chunks of 256 rows
    const int arr   = blockIdx.z;
    const float* __restrict__ p = arr ? g_py : g_px;
    const int r0 = chunk * (NROWS / 32);
    float sum = 0.f;
#pragma unroll 4
    for (int r = 0; r < NROWS / 32; r++)
        sum += p[(size_t)(r0 + r) * NCOLS + col];
    g_margpart[arr][chunk][col] = sum;
}

// ---------------------------------------------------------------------------
// Kernel 3: reduce partials -> log(marginal + eps)
// ---------------------------------------------------------------------------
__global__ __launch_bounds__(256) void logmarg_kernel() {
    const int col = blockIdx.x * 256 + threadIdx.x;
    const int arr = blockIdx.y;
    float sum = 0.f;
#pragma unroll
    for (int i = 0; i < 32; i++) sum += g_margpart[arr][i][col];
    g_lm[arr][col] = logf(sum * (1.0f / NROWS) + EPSF);
}

// ---------------------------------------------------------------------------
// Kernel 4: GEMM joint = PX^T * PY / N with fused MI epilogue.
// A[k][m] = px[k][m], B[k][n] = py[k][n] (both K-major, contiguous in m/n).
// 128x128 tile, BK=8, 256 threads, 8x8 per thread.
// ---------------------------------------------------------------------------
__global__ __launch_bounds__(256) void gemm_mi_kernel() {
    __shared__ float As[8][128];
    __shared__ float Bs[8][128];

    const int tid = threadIdx.x;
    const int bm  = blockIdx.x * 128;
    const int bn  = blockIdx.y * 128;

    const int lrow = tid >> 5;          // 0..7  (k within tile)
    const int lcol = (tid & 31) * 4;    // 0..124
    const float* __restrict__ aptr = g_px + (size_t)lrow * NCOLS + bm + lcol;
    const float* __restrict__ bptr = g_py + (size_t)lrow * NCOLS + bn + lcol;

    const int tx = tid & 15;            // m sub-tile
    const int ty = tid >> 4;            // n sub-tile

    float acc[8][8];
#pragma unroll
    for (int i = 0; i < 8; i++)
#pragma unroll
        for (int j = 0; j < 8; j++) acc[i][j] = 0.f;

    for (int k0 = 0; k0 < NROWS; k0 += 8) {
        const float4 a4 = *reinterpret_cast<const float4*>(aptr + (size_t)k0 * NCOLS);
        const float4 b4 = *reinterpret_cast<const float4*>(bptr + (size_t)k0 * NCOLS);
        __syncthreads();
        *reinterpret_cast<float4*>(&As[lrow][lcol]) = a4;
        *reinterpret_cast<float4*>(&Bs[lrow][lcol]) = b4;
        __syncthreads();
#pragma unroll
        for (int kk = 0; kk < 8; kk++) {
            float a[8], b[8];
            *reinterpret_cast<float4*>(a)     = *reinterpret_cast<const float4*>(&As[kk][tx * 4]);
            *reinterpret_cast<float4*>(a + 4) = *reinterpret_cast<const float4*>(&As[kk][64 + tx * 4]);
            *reinterpret_cast<float4*>(b)     = *reinterpret_cast<const float4*>(&Bs[kk][ty * 4]);
            *reinterpret_cast<float4*>(b + 4) = *reinterpret_cast<const float4*>(&Bs[kk][64 + ty * 4]);
#pragma unroll
            for (int i = 0; i < 8; i++)
#pragma unroll
                for (int j = 0; j < 8; j++)
                    acc[i][j] = fmaf(a[i], b[j], acc[i][j]);
        }
    }

    // ---- fused MI epilogue ----
    const float invn = 1.0f / NROWS;
    float lmx[8], lmy[8];
#pragma unroll
    for (int i = 0; i < 8; i++) {
        const int mi = bm + ((i < 4) ? (tx * 4 + i) : (64 + tx * 4 + i - 4));
        lmx[i] = g_lm[0][mi];
    }
#pragma unroll
    for (int j = 0; j < 8; j++) {
        const int nj = bn + ((j < 4) ? (ty * 4 + j) : (64 + ty * 4 + j - 4));
        lmy[j] = g_lm[1][nj];
    }

    double lsum = 0.0;
#pragma unroll
    for (int i = 0; i < 8; i++) {
#pragma unroll
        for (int j = 0; j < 8; j++) {
            const float joint = acc[i][j] * invn;
            const float term  = joint * (__logf(joint + EPSF) - lmx[i] - lmy[j]);
            lsum += (double)term;
        }
    }

    __shared__ double dred[256];
    dred[tid] = lsum;
    __syncthreads();
#pragma unroll
    for (int s = 128; s > 0; s >>= 1) {
        if (tid < s) dred[tid] += dred[tid + s];
        __syncthreads();
    }
    if (tid == 0) atomicAdd(&g_mi, dred[0]);
}

// ---------------------------------------------------------------------------
// Kernel 5: finalize — deterministic row-entropy reduction + output
// ---------------------------------------------------------------------------
__global__ __launch_bounds__(256) void finalize_kernel(float* __restrict__ out) {
    __shared__ float red[256];
    const int tid = threadIdx.x;
    float s = 0.f;
    for (int i = tid; i < NROWS; i += 256) s += g_rowent[i];
    red[tid] = s;
    __syncthreads();
#pragma unroll
    for (int o = 128; o > 0; o >>= 1) {
        if (tid < o) red[tid] += red[tid + o];
        __syncthreads();
    }
    if (tid == 0) {
        out[0] = red[0] * (1.0f / NROWS);
        out[1] = (float)g_mi;
    }
}

// ---------------------------------------------------------------------------
extern "C" void kernel_launch(void* const* d_in, const int* in_sizes, int n_in,
                              void* d_out, int out_size) {
    const float* X = (const float*)d_in[0];
    const float* Y = (const float*)d_in[1];
    float* out = (float*)d_out;

    init_kernel<<<1, 1>>>();
    softmax_kernel<<<2 * NROWS, 256>>>(X, Y);
    marg_kernel<<<dim3(NCOLS / 256, 32, 2), 256>>>();
    logmarg_kernel<<<dim3(NCOLS / 256, 2), 256>>>();
    gemm_mi_kernel<<<dim3(NCOLS / 128, NCOLS / 128), 256>>>();
    finalize_kernel<<<1, 256>>>(out);
}

// round 12
// speedup vs baseline: 5.3950x; 5.3950x over previous
#include <cuda_runtime.h>
#include <cuda_bf16.h>
#include <math_constants.h>
#include <cstdint>

// Problem constants
#define NROWS 8192
#define NCOLS 4096
#define EPSF 1e-12f

// GEMM tiling (bf16 operands, mma.sync m16n8k16)
#define BM 128
#define BN 128
#define BK 32                         // bf16 K elements per stage
#define NSTAGE (NROWS / BK)           // 256
#define AROW 40                       // padded row: 32 bf16 + 8 pad = 80 bytes
#define ATILE_B (BM * AROW * 2)       // 10240 bytes
#define BTILE_B (BN * AROW * 2)       // 10240 bytes

// ---------------------------------------------------------------------------
// Scratch (static device globals; no dynamic allocation allowed)
// ---------------------------------------------------------------------------
__device__ float          g_px[(size_t)NROWS * NCOLS];   // softmax(act_X) [NROWS][NCOLS]
__device__ float          g_py[(size_t)NROWS * NCOLS];   // softmax(act_Y)
__device__ __nv_bfloat16  g_pxt[(size_t)NROWS * NCOLS];  // bf16 transposed [NCOLS][NROWS]
__device__ __nv_bfloat16  g_pyt[(size_t)NROWS * NCOLS];
__device__ float          g_rowent[NROWS];               // per-row entropy of X
__device__ float          g_margpart[2][32][NCOLS];      // chunked column partial sums
__device__ float          g_lm[2][NCOLS];                // log(marg + eps)
__device__ double         g_mi;                          // MI accumulator

__device__ __forceinline__ uint32_t smem_u32(const void* p) {
    uint32_t a;
    asm("{ .reg .u64 t; cvta.to.shared.u64 t, %1; cvt.u32.u64 %0, t; }" : "=r"(a) : "l"(p));
    return a;
}

// ---------------------------------------------------------------------------
// Kernel 0: reset accumulators (graph is replayed; globals persist)
// ---------------------------------------------------------------------------
__global__ void init_kernel() { g_mi = 0.0; }

// ---------------------------------------------------------------------------
// Kernel 1: row softmax for X and Y (one block per row), fused entropy for X.
// entropy_row = log(Z) - S/Z  with  Z = sum exp(x-m),  S = sum (x-m)exp(x-m)
// ---------------------------------------------------------------------------
__global__ __launch_bounds__(256) void softmax_kernel(const float* __restrict__ X,
                                                      const float* __restrict__ Y) {
    const int row  = blockIdx.x;
    const bool isX = row < NROWS;
    const int r    = isX ? row : row - NROWS;
    const float* __restrict__ src = (isX ? X : Y) + (size_t)r * NCOLS;
    float* __restrict__ dst       = (isX ? g_px : g_py) + (size_t)r * NCOLS;

    const int tid = threadIdx.x;
    float4 v[4];
#pragma unroll
    for (int i = 0; i < 4; i++)
        v[i] = reinterpret_cast<const float4*>(src)[tid + i * 256];

    float m = -CUDART_INF_F;
#pragma unroll
    for (int i = 0; i < 4; i++)
        m = fmaxf(m, fmaxf(fmaxf(v[i].x, v[i].y), fmaxf(v[i].z, v[i].w)));
    __shared__ float sh_max[8];
#pragma unroll
    for (int o = 16; o > 0; o >>= 1) m = fmaxf(m, __shfl_xor_sync(0xffffffffu, m, o));
    if ((tid & 31) == 0) sh_max[tid >> 5] = m;
    __syncthreads();
    m = sh_max[0];
#pragma unroll
    for (int i = 1; i < 8; i++) m = fmaxf(m, sh_max[i]);
    __syncthreads();

    float z = 0.f, s = 0.f;
#pragma unroll
    for (int i = 0; i < 4; i++) {
        float t0 = v[i].x - m, t1 = v[i].y - m, t2 = v[i].z - m, t3 = v[i].w - m;
        float e0 = __expf(t0), e1 = __expf(t1), e2 = __expf(t2), e3 = __expf(t3);
        z += (e0 + e1) + (e2 + e3);
        s += (e0 * t0 + e1 * t1) + (e2 * t2 + e3 * t3);
        v[i].x = e0; v[i].y = e1; v[i].z = e2; v[i].w = e3;
    }
    __shared__ float sh_z[8], sh_s[8];
#pragma unroll
    for (int o = 16; o > 0; o >>= 1) {
        z += __shfl_xor_sync(0xffffffffu, z, o);
        s += __shfl_xor_sync(0xffffffffu, s, o);
    }
    if ((tid & 31) == 0) { sh_z[tid >> 5] = z; sh_s[tid >> 5] = s; }
    __syncthreads();
    z = 0.f; s = 0.f;
#pragma unroll
    for (int i = 0; i < 8; i++) { z += sh_z[i]; s += sh_s[i]; }

    const float invz = 1.0f / z;
#pragma unroll
    for (int i = 0; i < 4; i++) {
        float4 p;
        p.x = v[i].x * invz; p.y = v[i].y * invz;
        p.z = v[i].z * invz; p.w = v[i].w * invz;
        reinterpret_cast<float4*>(dst)[tid + i * 256] = p;
    }
    if (isX && tid == 0)
        g_rowent[r] = logf(z) - s * invz;
}

// ---------------------------------------------------------------------------
// Kernel 1b: tiled transpose + fp32->bf16 convert.
// src [NROWS][NCOLS] fp32 -> dst [NCOLS][NROWS] bf16 (bf16x2-packed stores).
// ---------------------------------------------------------------------------
__global__ __launch_bounds__(256) void transpose_kernel() {
    __shared__ float t[32][33];
    const int mat = blockIdx.z;
    const float* __restrict__ src = mat ? g_py : g_px;
    __nv_bfloat16* __restrict__ dst = mat ? g_pyt : g_pxt;
    const int c0 = blockIdx.x * 32;
    const int r0 = blockIdx.y * 32;
    const int tx = threadIdx.x & 31;
    const int ty = threadIdx.x >> 5;
#pragma unroll
    for (int i = 0; i < 4; i++)
        t[ty + i * 8][tx] = src[(size_t)(r0 + ty + i * 8) * NCOLS + c0 + tx];
    __syncthreads();
#pragma unroll
    for (int i = 0; i < 2; i++) {
        const int lin = threadIdx.x + i * 256;
        const int c  = lin >> 4;
        const int rp = lin & 15;
        __nv_bfloat162 p;
        p.x = __float2bfloat16(t[2 * rp][c]);
        p.y = __float2bfloat16(t[2 * rp + 1][c]);
        *reinterpret_cast<__nv_bfloat162*>(
            &dst[(size_t)(c0 + c) * NROWS + r0 + 2 * rp]) = p;
    }
}

// ---------------------------------------------------------------------------
// Kernel 2: chunked column sums (deterministic partials, fp32 inputs)
// ---------------------------------------------------------------------------
__global__ __launch_bounds__(256) void marg_kernel() {
    const int col   = blockIdx.x * 256 + threadIdx.x;
    const int chunk = blockIdx.y;
    const int arr   = blockIdx.z;
    const float* __restrict__ p = arr ? g_py : g_px;
    const int r0 = chunk * (NROWS / 32);
    float sum = 0.f;
#pragma unroll 4
    for (int r = 0; r < NROWS / 32; r++)
        sum += p[(size_t)(r0 + r) * NCOLS + col];
    g_margpart[arr][chunk][col] = sum;
}

// ---------------------------------------------------------------------------
// Kernel 3: reduce partials -> log(marginal + eps)
// ---------------------------------------------------------------------------
__global__ __launch_bounds__(256) void logmarg_kernel() {
    const int col = blockIdx.x * 256 + threadIdx.x;
    const int arr = blockIdx.y;
    float sum = 0.f;
#pragma unroll
    for (int i = 0; i < 32; i++) sum += g_margpart[arr][i][col];
    g_lm[arr][col] = logf(sum * (1.0f / NROWS) + EPSF);
}

// ---------------------------------------------------------------------------
// Kernel 4: bf16 GEMM joint = pxt * pyt^T / N via mma.sync.m16n8k16 (HMMA),
// fused MI epilogue. 128x128 tile, BK=32, 8 warps (2 m-halves x 4 n-quarters),
// each warp 64x32 = 4x4 m16n8k16 atoms. ldmatrix from padded SMEM (80B rows,
// conflict-free). Register prefetch overlaps LDG with MMA.
// ---------------------------------------------------------------------------
__global__ __launch_bounds__(256, 2) void gemm_mi_kernel() {
    __shared__ __align__(16) char sm_raw[ATILE_B + BTILE_B];
    __nv_bfloat16* As = reinterpret_cast<__nv_bfloat16*>(sm_raw);
    __nv_bfloat16* Bs = reinterpret_cast<__nv_bfloat16*>(sm_raw + ATILE_B);

    const int tid  = threadIdx.x;
    const int wid  = tid >> 5;
    const int lane = tid & 31;

    // grouped rasterization: 8 m-tiles per group for L2 reuse
    const int pid = blockIdx.x;
    const int pm  = ((pid >> 8) << 3) + (pid & 7);
    const int pn  = (pid & 255) >> 3;
    const int bm = pm * BM, bn = pn * BN;
    const float invn = 1.0f / NROWS;

    // ---- load slots: 2 x 16B chunks per operand per thread (512 chunks) ----
    const __nv_bfloat16* srcA[2]; const __nv_bfloat16* srcB[2];
    int dstOff[2];
#pragma unroll
    for (int i = 0; i < 2; i++) {
        const int c = tid + i * 256;        // 0..511
        const int row = c >> 2, q = c & 3;  // tile row, 16B chunk in row
        dstOff[i] = row * AROW + q * 8;     // bf16 elements
        srcA[i] = g_pxt + (size_t)(bm + row) * NROWS + q * 8;
        srcB[i] = g_pyt + (size_t)(bn + row) * NROWS + q * 8;
    }

    // ---- ldmatrix lane addressing ----
    const int wm = wid & 1;                 // m half (64)
    const int wn = wid >> 1;                // n quarter (32)
    const uint32_t As_b = smem_u32(As);
    const uint32_t Bs_b = smem_u32(Bs);
    const int r8   = lane & 7;
    const int quad = lane >> 3;             // A x4: quadrant 0..3
    uint32_t a_addr[4], b_addr[4];
#pragma unroll
    for (int mf = 0; mf < 4; mf++)
        a_addr[mf] = As_b + (uint32_t)(((wm * 64 + mf * 16) + (quad & 1) * 8 + r8) * (AROW * 2)
                                       + (quad >> 1) * 16);
    const int bhalf = (lane >> 3) & 1;      // B x2: matrix 0/1 (k halves)
#pragma unroll
    for (int nf = 0; nf < 4; nf++)
        b_addr[nf] = Bs_b + (uint32_t)(((wn * 32 + nf * 8) + r8) * (AROW * 2) + bhalf * 16);

    float acc[4][4][4];
#pragma unroll
    for (int i = 0; i < 4; i++)
#pragma unroll
        for (int j = 0; j < 4; j++)
#pragma unroll
            for (int k = 0; k < 4; k++) acc[i][j][k] = 0.f;

    // preload stage 0 into registers
    uint4 ra[2], rb[2];
#pragma unroll
    for (int i = 0; i < 2; i++) {
        ra[i] = *reinterpret_cast<const uint4*>(srcA[i]);
        rb[i] = *reinterpret_cast<const uint4*>(srcB[i]);
    }

    for (int s = 0; s < NSTAGE; s++) {
#pragma unroll
        for (int i = 0; i < 2; i++) {
            *reinterpret_cast<uint4*>(As + dstOff[i]) = ra[i];
            *reinterpret_cast<uint4*>(Bs + dstOff[i]) = rb[i];
        }
        __syncthreads();

        // prefetch stage s+1 (LDG in flight during the MMA work below)
        if (s + 1 < NSTAGE) {
#pragma unroll
            for (int i = 0; i < 2; i++) {
                ra[i] = *reinterpret_cast<const uint4*>(srcA[i] + (size_t)(s + 1) * BK);
                rb[i] = *reinterpret_cast<const uint4*>(srcB[i] + (size_t)(s + 1) * BK);
            }
        }

#pragma unroll
        for (int ks = 0; ks < 2; ks++) {            // two k16 steps (byte offset +32)
            const uint32_t ko = ks * 32;
            uint32_t a[4][4], b[4][2];
#pragma unroll
            for (int mf = 0; mf < 4; mf++)
                asm volatile("ldmatrix.sync.aligned.m8n8.x4.shared.b16 {%0,%1,%2,%3}, [%4];"
                    : "=r"(a[mf][0]), "=r"(a[mf][1]), "=r"(a[mf][2]), "=r"(a[mf][3])
                    : "r"(a_addr[mf] + ko));
#pragma unroll
            for (int nf = 0; nf < 4; nf++)
                asm volatile("ldmatrix.sync.aligned.m8n8.x2.shared.b16 {%0,%1}, [%2];"
                    : "=r"(b[nf][0]), "=r"(b[nf][1])
                    : "r"(b_addr[nf] + ko));
#pragma unroll
            for (int mf = 0; mf < 4; mf++)
#pragma unroll
                for (int nf = 0; nf < 4; nf++)
                    asm volatile("mma.sync.aligned.m16n8k16.row.col.f32.bf16.bf16.f32 "
                        "{%0,%1,%2,%3}, {%4,%5,%6,%7}, {%8,%9}, {%0,%1,%2,%3};"
                        : "+f"(acc[mf][nf][0]), "+f"(acc[mf][nf][1]),
                          "+f"(acc[mf][nf][2]), "+f"(acc[mf][nf][3])
                        : "r"(a[mf][0]), "r"(a[mf][1]), "r"(a[mf][2]), "r"(a[mf][3]),
                          "r"(b[nf][0]), "r"(b[nf][1]));
        }
        __syncthreads();
    }

    // ---- fused MI epilogue ----
    // acc[mf][nf]: c0: (row=lane>>2, col=(lane&3)*2), c1: col+1, c2: row+8, c3: row+8,col+1
    const int mrow = lane >> 2;
    const int ncol = (lane & 3) * 2;
    double lsum = 0.0;
#pragma unroll
    for (int mf = 0; mf < 4; mf++) {
        const int m0 = bm + wm * 64 + mf * 16 + mrow;
        const float lmx0 = g_lm[0][m0];
        const float lmx1 = g_lm[0][m0 + 8];
#pragma unroll
        for (int nf = 0; nf < 4; nf++) {
            const int n0 = bn + wn * 32 + nf * 8 + ncol;
            const float lmy0 = g_lm[1][n0];
            const float lmy1 = g_lm[1][n0 + 1];
            const float j0 = acc[mf][nf][0] * invn;
            const float j1 = acc[mf][nf][1] * invn;
            const float j2 = acc[mf][nf][2] * invn;
            const float j3 = acc[mf][nf][3] * invn;
            lsum += (double)(j0 * (__logf(j0 + EPSF) - lmx0 - lmy0));
            lsum += (double)(j1 * (__logf(j1 + EPSF) - lmx0 - lmy1));
            lsum += (double)(j2 * (__logf(j2 + EPSF) - lmx1 - lmy0));
            lsum += (double)(j3 * (__logf(j3 + EPSF) - lmx1 - lmy1));
        }
    }

    __syncthreads();
    double* red = reinterpret_cast<double*>(sm_raw);
    red[tid] = lsum;
    __syncthreads();
#pragma unroll
    for (int o = 128; o > 0; o >>= 1) {
        if (tid < o) red[tid] += red[tid + o];
        __syncthreads();
    }
    if (tid == 0) atomicAdd(&g_mi, red[0]);
}

// ---------------------------------------------------------------------------
// Kernel 5: finalize — deterministic row-entropy reduction + output
// ---------------------------------------------------------------------------
__global__ __launch_bounds__(256) void finalize_kernel(float* __restrict__ out) {
    __shared__ float red[256];
    const int tid = threadIdx.x;
    float s = 0.f;
    for (int i = tid; i < NROWS; i += 256) s += g_rowent[i];
    red[tid] = s;
    __syncthreads();
#pragma unroll
    for (int o = 128; o > 0; o >>= 1) {
        if (tid < o) red[tid] += red[tid + o];
        __syncthreads();
    }
    if (tid == 0) {
        out[0] = red[0] * (1.0f / NROWS);
        out[1] = (float)g_mi;
    }
}

// ---------------------------------------------------------------------------
extern "C" void kernel_launch(void* const* d_in, const int* in_sizes, int n_in,
                              void* d_out, int out_size) {
    const float* X = (const float*)d_in[0];
    const float* Y = (const float*)d_in[1];
    float* out = (float*)d_out;

    init_kernel<<<1, 1>>>();
    softmax_kernel<<<2 * NROWS, 256>>>(X, Y);
    transpose_kernel<<<dim3(NCOLS / 32, NROWS / 32, 2), 256>>>();
    marg_kernel<<<dim3(NCOLS / 256, 32, 2), 256>>>();
    logmarg_kernel<<<dim3(NCOLS / 256, 2), 256>>>();
    gemm_mi_kernel<<<(NCOLS / BM) * (NCOLS / BN), 256>>>();
    finalize_kernel<<<1, 256>>>(out);
}

// round 13
// speedup vs baseline: 6.0283x; 1.1174x over previous
#include <cuda_runtime.h>
#include <cuda_bf16.h>
#include <math_constants.h>
#include <cstdint>

// Problem constants
#define NROWS 8192
#define NCOLS 4096
#define EPSF 1e-12f

// GEMM tiling (bf16 operands, mma.sync m16n8k16), double-buffered
#define BM 128
#define BN 128
#define BK 64                         // bf16 K elements per stage
#define NSTAGE (NROWS / BK)           // 128
#define AROW 72                       // padded row: 64 bf16 + 8 pad = 144 bytes
#define ATILE_B (BM * AROW * 2)       // 18432 bytes per operand tile
#define STAGE_B (2 * ATILE_B)         // 36864 bytes (A + B)
#define GEMM_SMEM (2 * STAGE_B)       // 73728 bytes (double buffer)

// ---------------------------------------------------------------------------
// Scratch (static device globals; no dynamic allocation allowed)
// ---------------------------------------------------------------------------
__device__ float          g_px[(size_t)NROWS * NCOLS];   // softmax(act_X) [NROWS][NCOLS]
__device__ float          g_py[(size_t)NROWS * NCOLS];   // softmax(act_Y)
__device__ __nv_bfloat16  g_pxt[(size_t)NROWS * NCOLS];  // bf16 transposed [NCOLS][NROWS]
__device__ __nv_bfloat16  g_pyt[(size_t)NROWS * NCOLS];
__device__ float          g_rowent[NROWS];               // per-row entropy of X
__device__ float          g_margpart[2][32][NCOLS];      // chunked column partial sums
__device__ float          g_lm[2][NCOLS];                // log(marg + eps)
__device__ double         g_mi;                          // MI accumulator

__device__ __forceinline__ uint32_t smem_u32(const void* p) {
    uint32_t a;
    asm("{ .reg .u64 t; cvta.to.shared.u64 t, %1; cvt.u32.u64 %0, t; }" : "=r"(a) : "l"(p));
    return a;
}

// ---------------------------------------------------------------------------
// Kernel 0: reset accumulators (graph is replayed; globals persist)
// ---------------------------------------------------------------------------
__global__ void init_kernel() { g_mi = 0.0; }

// ---------------------------------------------------------------------------
// Kernel 1: row softmax for X and Y (one block per row), fused entropy for X.
// entropy_row = log(Z) - S/Z  with  Z = sum exp(x-m),  S = sum (x-m)exp(x-m)
// ---------------------------------------------------------------------------
__global__ __launch_bounds__(256) void softmax_kernel(const float* __restrict__ X,
                                                      const float* __restrict__ Y) {
    const int row  = blockIdx.x;
    const bool isX = row < NROWS;
    const int r    = isX ? row : row - NROWS;
    const float* __restrict__ src = (isX ? X : Y) + (size_t)r * NCOLS;
    float* __restrict__ dst       = (isX ? g_px : g_py) + (size_t)r * NCOLS;

    const int tid = threadIdx.x;
    float4 v[4];
#pragma unroll
    for (int i = 0; i < 4; i++)
        v[i] = reinterpret_cast<const float4*>(src)[tid + i * 256];

    float m = -CUDART_INF_F;
#pragma unroll
    for (int i = 0; i < 4; i++)
        m = fmaxf(m, fmaxf(fmaxf(v[i].x, v[i].y), fmaxf(v[i].z, v[i].w)));
    __shared__ float sh_max[8];
#pragma unroll
    for (int o = 16; o > 0; o >>= 1) m = fmaxf(m, __shfl_xor_sync(0xffffffffu, m, o));
    if ((tid & 31) == 0) sh_max[tid >> 5] = m;
    __syncthreads();
    m = sh_max[0];
#pragma unroll
    for (int i = 1; i < 8; i++) m = fmaxf(m, sh_max[i]);
    __syncthreads();

    float z = 0.f, s = 0.f;
#pragma unroll
    for (int i = 0; i < 4; i++) {
        float t0 = v[i].x - m, t1 = v[i].y - m, t2 = v[i].z - m, t3 = v[i].w - m;
        float e0 = __expf(t0), e1 = __expf(t1), e2 = __expf(t2), e3 = __expf(t3);
        z += (e0 + e1) + (e2 + e3);
        s += (e0 * t0 + e1 * t1) + (e2 * t2 + e3 * t3);
        v[i].x = e0; v[i].y = e1; v[i].z = e2; v[i].w = e3;
    }
    __shared__ float sh_z[8], sh_s[8];
#pragma unroll
    for (int o = 16; o > 0; o >>= 1) {
        z += __shfl_xor_sync(0xffffffffu, z, o);
        s += __shfl_xor_sync(0xffffffffu, s, o);
    }
    if ((tid & 31) == 0) { sh_z[tid >> 5] = z; sh_s[tid >> 5] = s; }
    __syncthreads();
    z = 0.f; s = 0.f;
#pragma unroll
    for (int i = 0; i < 8; i++) { z += sh_z[i]; s += sh_s[i]; }

    const float invz = 1.0f / z;
#pragma unroll
    for (int i = 0; i < 4; i++) {
        float4 p;
        p.x = v[i].x * invz; p.y = v[i].y * invz;
        p.z = v[i].z * invz; p.w = v[i].w * invz;
        reinterpret_cast<float4*>(dst)[tid + i * 256] = p;
    }
    if (isX && tid == 0)
        g_rowent[r] = logf(z) - s * invz;
}

// ---------------------------------------------------------------------------
// Kernel 1b: tiled transpose + fp32->bf16 convert.
// src [NROWS][NCOLS] fp32 -> dst [NCOLS][NROWS] bf16 (bf16x2-packed stores).
// ---------------------------------------------------------------------------
__global__ __launch_bounds__(256) void transpose_kernel() {
    __shared__ float t[32][33];
    const int mat = blockIdx.z;
    const float* __restrict__ src = mat ? g_py : g_px;
    __nv_bfloat16* __restrict__ dst = mat ? g_pyt : g_pxt;
    const int c0 = blockIdx.x * 32;
    const int r0 = blockIdx.y * 32;
    const int tx = threadIdx.x & 31;
    const int ty = threadIdx.x >> 5;
#pragma unroll
    for (int i = 0; i < 4; i++)
        t[ty + i * 8][tx] = src[(size_t)(r0 + ty + i * 8) * NCOLS + c0 + tx];
    __syncthreads();
#pragma unroll
    for (int i = 0; i < 2; i++) {
        const int lin = threadIdx.x + i * 256;
        const int c  = lin >> 4;
        const int rp = lin & 15;
        __nv_bfloat162 p;
        p.x = __float2bfloat16(t[2 * rp][c]);
        p.y = __float2bfloat16(t[2 * rp + 1][c]);
        *reinterpret_cast<__nv_bfloat162*>(
            &dst[(size_t)(c0 + c) * NROWS + r0 + 2 * rp]) = p;
    }
}

// ---------------------------------------------------------------------------
// Kernel 2: chunked column sums (deterministic partials, fp32 inputs)
// ---------------------------------------------------------------------------
__global__ __launch_bounds__(256) void marg_kernel() {
    const int col   = blockIdx.x * 256 + threadIdx.x;
    const int chunk = blockIdx.y;
    const int arr   = blockIdx.z;
    const float* __restrict__ p = arr ? g_py : g_px;
    const int r0 = chunk * (NROWS / 32);
    float sum = 0.f;
#pragma unroll 4
    for (int r = 0; r < NROWS / 32; r++)
        sum += p[(size_t)(r0 + r) * NCOLS + col];
    g_margpart[arr][chunk][col] = sum;
}

// ---------------------------------------------------------------------------
// Kernel 3: reduce partials -> log(marginal + eps)
// ---------------------------------------------------------------------------
__global__ __launch_bounds__(256) void logmarg_kernel() {
    const int col = blockIdx.x * 256 + threadIdx.x;
    const int arr = blockIdx.y;
    float sum = 0.f;
#pragma unroll
    for (int i = 0; i < 32; i++) sum += g_margpart[arr][i][col];
    g_lm[arr][col] = logf(sum * (1.0f / NROWS) + EPSF);
}

// ---------------------------------------------------------------------------
// Kernel 4: bf16 GEMM joint = pxt * pyt^T / N via mma.sync.m16n8k16 (HMMA),
// double-buffered SMEM (one __syncthreads per K-stage), BK=64, fused MI
// epilogue. 8 warps (2 m-halves x 4 n-quarters), each warp 64x32 output.
// Padded 144B SMEM rows keep ldmatrix conflict-free.
// ---------------------------------------------------------------------------
__global__ __launch_bounds__(256, 2) void gemm_mi_kernel() {
    extern __shared__ __align__(16) char sm_raw[];

    const int tid  = threadIdx.x;
    const int wid  = tid >> 5;
    const int lane = tid & 31;

    // grouped rasterization: 8 m-tiles per group for L2 reuse
    const int pid = blockIdx.x;
    const int pm  = ((pid >> 8) << 3) + (pid & 7);
    const int pn  = (pid & 255) >> 3;
    const int bm = pm * BM, bn = pn * BN;
    const float invn = 1.0f / NROWS;

    // ---- load slots: 4 x 16B chunks per operand per thread (1024 chunks) ----
    const __nv_bfloat16* srcA[4]; const __nv_bfloat16* srcB[4];
    int dstOff[4];
#pragma unroll
    for (int i = 0; i < 4; i++) {
        const int c = tid + i * 256;        // 0..1023
        const int row = c >> 3, q = c & 7;  // tile row, 16B chunk in row
        dstOff[i] = row * AROW + q * 8;     // bf16 elements
        srcA[i] = g_pxt + (size_t)(bm + row) * NROWS + q * 8;
        srcB[i] = g_pyt + (size_t)(bn + row) * NROWS + q * 8;
    }

    // ---- ldmatrix lane addressing (relative offsets within a stage buffer) ----
    const int wm = wid & 1;                 // m half (64)
    const int wn = wid >> 1;                // n quarter (32)
    const uint32_t sm_b = smem_u32(sm_raw);
    const int r8   = lane & 7;
    const int quad = lane >> 3;             // A x4: quadrant 0..3
    uint32_t a_off[4], b_off[4];
#pragma unroll
    for (int mf = 0; mf < 4; mf++)
        a_off[mf] = (uint32_t)(((wm * 64 + mf * 16) + (quad & 1) * 8 + r8) * (AROW * 2)
                               + (quad >> 1) * 16);
    const int bhalf = (lane >> 3) & 1;      // B x2: matrix 0/1 (k halves)
#pragma unroll
    for (int nf = 0; nf < 4; nf++)
        b_off[nf] = (uint32_t)(ATILE_B + ((wn * 32 + nf * 8) + r8) * (AROW * 2) + bhalf * 16);

    float acc[4][4][4];
#pragma unroll
    for (int i = 0; i < 4; i++)
#pragma unroll
        for (int j = 0; j < 4; j++)
#pragma unroll
            for (int k = 0; k < 4; k++) acc[i][j][k] = 0.f;

    // preload stage 0 and store into buffer 0
    uint4 ra[4], rb[4];
#pragma unroll
    for (int i = 0; i < 4; i++) {
        ra[i] = *reinterpret_cast<const uint4*>(srcA[i]);
        rb[i] = *reinterpret_cast<const uint4*>(srcB[i]);
    }
#pragma unroll
    for (int i = 0; i < 4; i++) {
        *reinterpret_cast<uint4*>(sm_raw + dstOff[i] * 2)           = ra[i];
        *reinterpret_cast<uint4*>(sm_raw + ATILE_B + dstOff[i] * 2) = rb[i];
    }
    __syncthreads();

    for (int s = 0; s < NSTAGE; s++) {
        const uint32_t bufb = sm_b + (uint32_t)((s & 1) * STAGE_B);

        // prefetch stage s+1 (LDG latency hidden under the MMA work below)
        if (s + 1 < NSTAGE) {
#pragma unroll
            for (int i = 0; i < 4; i++) {
                ra[i] = *reinterpret_cast<const uint4*>(srcA[i] + (size_t)(s + 1) * BK);
                rb[i] = *reinterpret_cast<const uint4*>(srcB[i] + (size_t)(s + 1) * BK);
            }
        }

#pragma unroll
        for (int ks = 0; ks < 4; ks++) {            // four k16 steps (byte offset +32)
            const uint32_t ko = ks * 32;
            uint32_t a[4][4], b[4][2];
#pragma unroll
            for (int mf = 0; mf < 4; mf++)
                asm volatile("ldmatrix.sync.aligned.m8n8.x4.shared.b16 {%0,%1,%2,%3}, [%4];"
                    : "=r"(a[mf][0]), "=r"(a[mf][1]), "=r"(a[mf][2]), "=r"(a[mf][3])
                    : "r"(bufb + a_off[mf] + ko));
#pragma unroll
            for (int nf = 0; nf < 4; nf++)
                asm volatile("ldmatrix.sync.aligned.m8n8.x2.shared.b16 {%0,%1}, [%2];"
                    : "=r"(b[nf][0]), "=r"(b[nf][1])
                    : "r"(bufb + b_off[nf] + ko));
#pragma unroll
            for (int mf = 0; mf < 4; mf++)
#pragma unroll
                for (int nf = 0; nf < 4; nf++)
                    asm volatile("mma.sync.aligned.m16n8k16.row.col.f32.bf16.bf16.f32 "
                        "{%0,%1,%2,%3}, {%4,%5,%6,%7}, {%8,%9}, {%0,%1,%2,%3};"
                        : "+f"(acc[mf][nf][0]), "+f"(acc[mf][nf][1]),
                          "+f"(acc[mf][nf][2]), "+f"(acc[mf][nf][3])
                        : "r"(a[mf][0]), "r"(a[mf][1]), "r"(a[mf][2]), "r"(a[mf][3]),
                          "r"(b[nf][0]), "r"(b[nf][1]));
        }

        // store stage s+1 into the other buffer (no reader until next sync)
        if (s + 1 < NSTAGE) {
            char* nb = sm_raw + ((s + 1) & 1) * STAGE_B;
#pragma unroll
            for (int i = 0; i < 4; i++) {
                *reinterpret_cast<uint4*>(nb + dstOff[i] * 2)           = ra[i];
                *reinterpret_cast<uint4*>(nb + ATILE_B + dstOff[i] * 2) = rb[i];
            }
        }
        __syncthreads();
    }

    // ---- fused MI epilogue ----
    // acc[mf][nf]: c0: (row=lane>>2, col=(lane&3)*2), c1: col+1, c2: row+8, c3: row+8,col+1
    const int mrow = lane >> 2;
    const int ncol = (lane & 3) * 2;
    double lsum = 0.0;
#pragma unroll
    for (int mf = 0; mf < 4; mf++) {
        const int m0 = bm + wm * 64 + mf * 16 + mrow;
        const float lmx0 = g_lm[0][m0];
        const float lmx1 = g_lm[0][m0 + 8];
#pragma unroll
        for (int nf = 0; nf < 4; nf++) {
            const int n0 = bn + wn * 32 + nf * 8 + ncol;
            const float lmy0 = g_lm[1][n0];
            const float lmy1 = g_lm[1][n0 + 1];
            const float j0 = acc[mf][nf][0] * invn;
            const float j1 = acc[mf][nf][1] * invn;
            const float j2 = acc[mf][nf][2] * invn;
            const float j3 = acc[mf][nf][3] * invn;
            lsum += (double)(j0 * (__logf(j0 + EPSF) - lmx0 - lmy0));
            lsum += (double)(j1 * (__logf(j1 + EPSF) - lmx0 - lmy1));
            lsum += (double)(j2 * (__logf(j2 + EPSF) - lmx1 - lmy0));
            lsum += (double)(j3 * (__logf(j3 + EPSF) - lmx1 - lmy1));
        }
    }

    __syncthreads();
    double* red = reinterpret_cast<double*>(sm_raw);
    red[tid] = lsum;
    __syncthreads();
#pragma unroll
    for (int o = 128; o > 0; o >>= 1) {
        if (tid < o) red[tid] += red[tid + o];
        __syncthreads();
    }
    if (tid == 0) atomicAdd(&g_mi, red[0]);
}

// ---------------------------------------------------------------------------
// Kernel 5: finalize — deterministic row-entropy reduction + output
// ---------------------------------------------------------------------------
__global__ __launch_bounds__(256) void finalize_kernel(float* __restrict__ out) {
    __shared__ float red[256];
    const int tid = threadIdx.x;
    float s = 0.f;
    for (int i = tid; i < NROWS; i += 256) s += g_rowent[i];
    red[tid] = s;
    __syncthreads();
#pragma unroll
    for (int o = 128; o > 0; o >>= 1) {
        if (tid < o) red[tid] += red[tid + o];
        __syncthreads();
    }
    if (tid == 0) {
        out[0] = red[0] * (1.0f / NROWS);
        out[1] = (float)g_mi;
    }
}

// ---------------------------------------------------------------------------
extern "C" void kernel_launch(void* const* d_in, const int* in_sizes, int n_in,
                              void* d_out, int out_size) {
    const float* X = (const float*)d_in[0];
    const float* Y = (const float*)d_in[1];
    float* out = (float*)d_out;

    cudaFuncSetAttribute(gemm_mi_kernel,
                         cudaFuncAttributeMaxDynamicSharedMemorySize, GEMM_SMEM);

    init_kernel<<<1, 1>>>();
    softmax_kernel<<<2 * NROWS, 256>>>(X, Y);
    transpose_kernel<<<dim3(NCOLS / 32, NROWS / 32, 2), 256>>>();
    marg_kernel<<<dim3(NCOLS / 256, 32, 2), 256>>>();
    logmarg_kernel<<<dim3(NCOLS / 256, 2), 256>>>();
    gemm_mi_kernel<<<(NCOLS / BM) * (NCOLS / BN), 256, GEMM_SMEM>>>();
    finalize_kernel<<<1, 256>>>(out);
}